// round 3
// baseline (speedup 1.0000x reference)
#include <cuda_runtime.h>
#include <cuda_bf16.h>
#include <cstddef>

// ---------------------------------------------------------------------------
// Problem constants: B=8, T=1024, C=1024, H=16, hd=64, NQS=4
//   qkv  = x @ W_attn^T        : [8192, 6144]
//   attn : per (b,h,g) flash attention, hd=64, causal
//   y    : [8192, 4096] (concat of 4 query-set outputs)
//   out  = y @ W_proj^T        : [8192, 1024]
// ---------------------------------------------------------------------------

#define MB 8192           // B*T
#define CQKV 6144
#define CY 4096
#define CX 1024
#define HD 64
#define QT 64             // q rows per attention block
#define KT 32             // k rows per attention tile

__device__ float g_qkv[(size_t)MB * CQKV];   // 192 MB scratch
__device__ float g_y[(size_t)MB * CY];       // 128 MB scratch

// ---------------------------------------------------------------------------
// Generic NT GEMM: C[M,N] = A[M,K] * B[N,K]^T   (both row-major, K contiguous)
// 128x128 block, BK=16, 256 threads, 8x8 per thread.
// Requires M%128==0, N%128==0, K%16==0 (true for all three calls).
// ---------------------------------------------------------------------------
__global__ __launch_bounds__(256) void gemm_nt_kernel(
    const float* __restrict__ A, const float* __restrict__ B, float* __restrict__ C,
    int M, int N, int K)
{
    __shared__ float As[16][132];
    __shared__ float Bs[16][132];

    const int tid = threadIdx.x;
    const int bm = blockIdx.y * 128;
    const int bn = blockIdx.x * 128;
    const int tr = tid >> 4;    // 0..15
    const int tc = tid & 15;    // 0..15

    float acc[8][8];
#pragma unroll
    for (int i = 0; i < 8; i++)
#pragma unroll
        for (int j = 0; j < 8; j++) acc[i][j] = 0.f;

    const float* Aptr = A + (size_t)bm * K;
    const float* Bptr = B + (size_t)bn * K;

    for (int k0 = 0; k0 < K; k0 += 16) {
#pragma unroll
        for (int p = 0; p < 2; p++) {
            int idx = (p * 256 + tid) * 4;     // 0..2047, step 4
            int row = idx >> 4;                 // /16
            int kk  = idx & 15;                 // 0,4,8,12
            float4 va = *(const float4*)(Aptr + (size_t)row * K + k0 + kk);
            As[kk + 0][row] = va.x; As[kk + 1][row] = va.y;
            As[kk + 2][row] = va.z; As[kk + 3][row] = va.w;
            float4 vb = *(const float4*)(Bptr + (size_t)row * K + k0 + kk);
            Bs[kk + 0][row] = vb.x; Bs[kk + 1][row] = vb.y;
            Bs[kk + 2][row] = vb.z; Bs[kk + 3][row] = vb.w;
        }
        __syncthreads();
#pragma unroll
        for (int kk = 0; kk < 16; kk++) {
            float ra[8], rb[8];
#pragma unroll
            for (int i = 0; i < 8; i++) ra[i] = As[kk][tr * 8 + i];
#pragma unroll
            for (int j = 0; j < 8; j++) rb[j] = Bs[kk][tc * 8 + j];
#pragma unroll
            for (int i = 0; i < 8; i++)
#pragma unroll
                for (int j = 0; j < 8; j++)
                    acc[i][j] = fmaf(ra[i], rb[j], acc[i][j]);
        }
        __syncthreads();
    }

#pragma unroll
    for (int i = 0; i < 8; i++) {
        float* Crow = C + (size_t)(bm + tr * 8 + i) * N + bn + tc * 8;
        *(float4*)(Crow + 0) = make_float4(acc[i][0], acc[i][1], acc[i][2], acc[i][3]);
        *(float4*)(Crow + 4) = make_float4(acc[i][4], acc[i][5], acc[i][6], acc[i][7]);
    }
}

// ---------------------------------------------------------------------------
// Flash attention (fp32, causal), one block per (qt, g, b*16+h).
// Q tile = 64 rows, K/V tiles = 32 rows, hd = 64. Online softmax.
// ---------------------------------------------------------------------------
__global__ __launch_bounds__(256) void attn_kernel(
    const float* __restrict__ qkv, float* __restrict__ y)
{
    __shared__ float Qs[QT][HD + 4];      // 68-float rows (16B aligned)
    __shared__ float Ks[KT][HD + 4];
    __shared__ float Vs[KT][HD + 4];
    __shared__ float Ss[QT][KT + 4];      // 36-float rows (16B aligned)
    __shared__ float sm_m[QT], sm_l[QT], sm_a[QT];

    const int tid = threadIdx.x;
    const int qt = blockIdx.x;            // 0..15
    const int g  = blockIdx.y;            // 0..3
    const int bh = blockIdx.z;            // 0..127
    const int b = bh >> 4;
    const int h = bh & 15;

    const size_t rs = CQKV;               // qkv row stride
    const float* qbase = qkv + (size_t)(b * 1024 + qt * QT) * rs + g * 1024 + h * 64;
    const float* kbase = qkv + (size_t)(b * 1024) * rs + 4 * 1024 + h * 64;
    const float* vbase = qkv + (size_t)(b * 1024) * rs + 5 * 1024 + h * 64;

    // load Q tile (64x64)
#pragma unroll
    for (int p = 0; p < 4; p++) {
        int idx = (p * 256 + tid) * 4;
        int r = idx >> 6, d = idx & 63;
        *(float4*)&Qs[r][d] = *(const float4*)(qbase + (size_t)r * rs + d);
    }
    if (tid < QT) { sm_m[tid] = -1e30f; sm_l[tid] = 0.f; }

    float o[4][4];
#pragma unroll
    for (int i = 0; i < 4; i++)
#pragma unroll
        for (int j = 0; j < 4; j++) o[i][j] = 0.f;

    const int nkt = 2 * qt + 2;           // causal tile count
    const float scale = 0.125f;           // 1/sqrt(64)

    const int sr  = (tid >> 4) * 4;       // score rows (4)
    const int sc  = tid & 15;             // score cols {sc, sc+16}
    const int orr = (tid >> 4) * 4;       // O rows (4)
    const int oc  = (tid & 15) * 4;       // O cols (4)
    const int smr = tid >> 2;             // softmax row
    const int sml = tid & 3;              // softmax lane in quad

    for (int kt = 0; kt < nkt; kt++) {
        __syncthreads();                  // previous O-phase done with Ks/Vs/Ss
        // load K/V tiles (32x64 each)
#pragma unroll
        for (int p = 0; p < 2; p++) {
            int idx = (p * 256 + tid) * 4;
            int c = idx >> 6, d = idx & 63;
            *(float4*)&Ks[c][d] = *(const float4*)(kbase + (size_t)(kt * KT + c) * rs + d);
            *(float4*)&Vs[c][d] = *(const float4*)(vbase + (size_t)(kt * KT + c) * rs + d);
        }
        __syncthreads();

        // scores: S[sr+i][sc], S[sr+i][sc+16]
        {
            float s0[4], s1[4];
#pragma unroll
            for (int i = 0; i < 4; i++) { s0[i] = 0.f; s1[i] = 0.f; }
#pragma unroll
            for (int d = 0; d < HD; d += 4) {
                float4 k0 = *(const float4*)&Ks[sc][d];
                float4 k1 = *(const float4*)&Ks[sc + 16][d];
#pragma unroll
                for (int i = 0; i < 4; i++) {
                    float4 q = *(const float4*)&Qs[sr + i][d];
                    s0[i] += q.x * k0.x + q.y * k0.y + q.z * k0.z + q.w * k0.w;
                    s1[i] += q.x * k1.x + q.y * k1.y + q.z * k1.z + q.w * k1.w;
                }
            }
            int qg0 = qt * QT + sr;
            int kg0 = kt * KT + sc;
#pragma unroll
            for (int i = 0; i < 4; i++) {
                int qg = qg0 + i;
                Ss[sr + i][sc]      = (kg0      <= qg) ? s0[i] * scale : -1e30f;
                Ss[sr + i][sc + 16] = (kg0 + 16 <= qg) ? s1[i] * scale : -1e30f;
            }
        }
        __syncthreads();

        // online softmax per row (4 lanes per row)
        {
            float m_old = sm_m[smr];
            float l_old = sm_l[smr];
            float vals[8];
            float vmax = -1e30f;
#pragma unroll
            for (int j = 0; j < 8; j++) {
                vals[j] = Ss[smr][sml * 8 + j];
                vmax = fmaxf(vmax, vals[j]);
            }
            vmax = fmaxf(vmax, __shfl_xor_sync(0xFFFFFFFFu, vmax, 1));
            vmax = fmaxf(vmax, __shfl_xor_sync(0xFFFFFFFFu, vmax, 2));
            float m_new = fmaxf(m_old, vmax);
            float lsum = 0.f;
#pragma unroll
            for (int j = 0; j < 8; j++) {
                float pv = __expf(vals[j] - m_new);
                Ss[smr][sml * 8 + j] = pv;
                lsum += pv;
            }
            lsum += __shfl_xor_sync(0xFFFFFFFFu, lsum, 1);
            lsum += __shfl_xor_sync(0xFFFFFFFFu, lsum, 2);
            if (sml == 0) {
                float alpha = __expf(m_old - m_new);
                sm_m[smr] = m_new;
                sm_l[smr] = l_old * alpha + lsum;
                sm_a[smr] = alpha;
            }
        }
        __syncthreads();

        // O update: O = O*alpha + P @ V
        {
#pragma unroll
            for (int i = 0; i < 4; i++) {
                float a = sm_a[orr + i];
#pragma unroll
                for (int j = 0; j < 4; j++) o[i][j] *= a;
            }
#pragma unroll
            for (int k = 0; k < KT; k += 4) {
                float4 v0 = *(const float4*)&Vs[k + 0][oc];
                float4 v1 = *(const float4*)&Vs[k + 1][oc];
                float4 v2 = *(const float4*)&Vs[k + 2][oc];
                float4 v3 = *(const float4*)&Vs[k + 3][oc];
#pragma unroll
                for (int i = 0; i < 4; i++) {
                    float4 p4 = *(const float4*)&Ss[orr + i][k];
                    o[i][0] += p4.x * v0.x + p4.y * v1.x + p4.z * v2.x + p4.w * v3.x;
                    o[i][1] += p4.x * v0.y + p4.y * v1.y + p4.z * v2.y + p4.w * v3.y;
                    o[i][2] += p4.x * v0.z + p4.y * v1.z + p4.z * v2.z + p4.w * v3.z;
                    o[i][3] += p4.x * v0.w + p4.y * v1.w + p4.z * v2.w + p4.w * v3.w;
                }
            }
        }
    }

    // epilogue: divide by l, write to concat layout [b*T+t][g*1024 + h*64 + d]
    float* ybase = y + (size_t)(b * 1024 + qt * QT) * CY + g * 1024 + h * 64;
#pragma unroll
    for (int i = 0; i < 4; i++) {
        float inv = 1.f / sm_l[orr + i];
        float4 outv = make_float4(o[i][0] * inv, o[i][1] * inv, o[i][2] * inv, o[i][3] * inv);
        *(float4*)(ybase + (size_t)(orr + i) * CY + oc) = outv;
    }
}

// ---------------------------------------------------------------------------

extern "C" void kernel_launch(void* const* d_in, const int* in_sizes, int n_in,
                              void* d_out, int out_size)
{
    const float* x      = (const float*)d_in[0];   // [8,1024,1024]
    const float* W_attn = (const float*)d_in[1];   // [6144,1024]
    const float* W_proj = (const float*)d_in[2];   // [1024,4096]
    float* out = (float*)d_out;                    // [8,1024,1024]

    float* qkv_ptr = nullptr;
    float* y_ptr = nullptr;
    cudaGetSymbolAddress((void**)&qkv_ptr, g_qkv);
    cudaGetSymbolAddress((void**)&y_ptr, g_y);

    // 1) qkv = x @ W_attn^T   [8192 x 6144], K=1024
    {
        dim3 grid(CQKV / 128, MB / 128);
        gemm_nt_kernel<<<grid, 256>>>(x, W_attn, qkv_ptr, MB, CQKV, CX);
    }
    // 2) attention -> y  [8192 x 4096]
    {
        dim3 grid(1024 / QT, 4, 128);   // (q tiles, query sets, b*h)
        attn_kernel<<<grid, 256>>>(qkv_ptr, y_ptr);
    }
    // 3) out = y @ W_proj^T   [8192 x 1024], K=4096
    {
        dim3 grid(CX / 128, MB / 128);
        gemm_nt_kernel<<<grid, 256>>>(y_ptr, W_proj, out, MB, CX, CY);
    }
}

// round 12
// speedup vs baseline: 1.5312x; 1.5312x over previous
#include <cuda_runtime.h>
#include <cuda_bf16.h>
#include <cstdint>
#include <cstddef>

// ---------------------------------------------------------------------------
// B=8, T=1024, C=1024, H=16, hd=64, NQS=4
//   qkv  = x @ W_attn^T  [8192,6144]   (mma.sync split-bf16, 3-pass)
//   attn : flash fp32    -> y [8192,4096]
//   out  = y @ W_proj^T  [8192,1024]   (mma.sync split-bf16, 3-pass)
// NOTE: harness ptxas targets sm_103 (no 'a') -> tcgen05 PTX unavailable.
//       mma.sync/ldmatrix are sm_80-era PTX and compile fine.
// ---------------------------------------------------------------------------

#define MB 8192
#define CQKV 6144
#define CY 4096
#define CX 1024
#define HD 64
#define QT 64
#define KT 32
#define BKK 64          // GEMM K-chunk (128B bf16 rows -> swizzle<3,4,3>)

__device__ float g_qkv[(size_t)MB * CQKV];
__device__ float g_y[(size_t)MB * CY];
__device__ __nv_bfloat16 g_xhi[(size_t)MB * CX];
__device__ __nv_bfloat16 g_xlo[(size_t)MB * CX];
__device__ __nv_bfloat16 g_wahi[(size_t)CQKV * CX];
__device__ __nv_bfloat16 g_walo[(size_t)CQKV * CX];
__device__ __nv_bfloat16 g_yhi[(size_t)MB * CY];
__device__ __nv_bfloat16 g_ylo[(size_t)MB * CY];
__device__ __nv_bfloat16 g_wphi[(size_t)CX * CY];
__device__ __nv_bfloat16 g_wplo[(size_t)CX * CY];

__device__ __forceinline__ uint32_t smem_u32(const void* p) {
    uint32_t a;
    asm("{ .reg .u64 t; cvta.to.shared.u64 t, %1; cvt.u32.u64 %0, t; }" : "=r"(a) : "l"(p));
    return a;
}

__device__ __forceinline__ void ldmx4(uint32_t* r, uint32_t addr) {
    asm volatile("ldmatrix.sync.aligned.m8n8.x4.shared.b16 {%0,%1,%2,%3}, [%4];"
        : "=r"(r[0]), "=r"(r[1]), "=r"(r[2]), "=r"(r[3]) : "r"(addr));
}
__device__ __forceinline__ void ldmx2(uint32_t* r, uint32_t addr) {
    asm volatile("ldmatrix.sync.aligned.m8n8.x2.shared.b16 {%0,%1}, [%2];"
        : "=r"(r[0]), "=r"(r[1]) : "r"(addr));
}
__device__ __forceinline__ void mma16816(float* d, const uint32_t* a, const uint32_t* b) {
    asm volatile(
        "mma.sync.aligned.m16n8k16.row.col.f32.bf16.bf16.f32 "
        "{%0,%1,%2,%3}, {%4,%5,%6,%7}, {%8,%9}, {%0,%1,%2,%3};"
        : "+f"(d[0]), "+f"(d[1]), "+f"(d[2]), "+f"(d[3])
        : "r"(a[0]), "r"(a[1]), "r"(a[2]), "r"(a[3]), "r"(b[0]), "r"(b[1]));
}

// ---------------------------------------------------------------------------
// split fp32 -> hi/lo bf16 (3xBF16 trick). n % 4 == 0.
// ---------------------------------------------------------------------------
__global__ __launch_bounds__(256) void split_kernel(
    const float* __restrict__ s, __nv_bfloat16* __restrict__ hi,
    __nv_bfloat16* __restrict__ lo, int n)
{
    int i = (blockIdx.x * 256 + threadIdx.x) * 4;
    if (i >= n) return;
    float4 v = *(const float4*)(s + i);
    float f[4] = {v.x, v.y, v.z, v.w};
    union { __nv_bfloat16 b[4]; uint2 u; } H, L;
#pragma unroll
    for (int j = 0; j < 4; j++) {
        H.b[j] = __float2bfloat16(f[j]);
        L.b[j] = __float2bfloat16(f[j] - __bfloat162float(H.b[j]));
    }
    *(uint2*)(hi + i) = H.u;
    *(uint2*)(lo + i) = L.u;
}

// ---------------------------------------------------------------------------
// mma.sync split-bf16 NT GEMM: C = (Ahi+Alo)(Bhi+Blo)^T, lo*lo dropped.
// CTA 128x128, BK=64. 256 threads = 8 warps (2M x 4N), 64x32 per warp.
// Swizzle<3,4,3>: off = r*128 + ((ck ^ (r&7))*16), ck = k/8.
// ---------------------------------------------------------------------------
__global__ __launch_bounds__(256) void gemm_mma_kernel(
    const __nv_bfloat16* __restrict__ Ahi, const __nv_bfloat16* __restrict__ Alo,
    const __nv_bfloat16* __restrict__ Bhi, const __nv_bfloat16* __restrict__ Blo,
    float* __restrict__ C, int M, int N, int K)
{
    extern __shared__ __align__(128) char smem[];
    // tiles: [0]=Ahi [16K]=Alo [32K]=Bhi [48K]=Blo, each 128x64 bf16 = 16KB
    const uint32_t sb = smem_u32(smem);
    const int tid = threadIdx.x;
    const int wid = tid >> 5, lane = tid & 31;
    const int bm = blockIdx.y * 128, bn = blockIdx.x * 128;
    const int wm = (wid >> 2) * 64;        // 0 or 64
    const int wn = (wid & 3) * 32;         // 0,32,64,96

    const __nv_bfloat16* srcs[4] = {
        Ahi + (size_t)bm * K, Alo + (size_t)bm * K,
        Bhi + (size_t)bn * K, Blo + (size_t)bn * K };

    float acc[4][4][4];
#pragma unroll
    for (int i = 0; i < 4; i++)
#pragma unroll
        for (int j = 0; j < 4; j++)
#pragma unroll
            for (int e = 0; e < 4; e++) acc[i][j][e] = 0.f;

    // ldmatrix base offsets (per lane), swizzled chunk addressing
    const int a_r = lane & 15, a_c = lane >> 4;        // A: row, k-chunk half
    const int b_r = lane & 7,  b_c = (lane >> 3) & 1;  // B: row, k-chunk half

    for (int k0 = 0; k0 < K; k0 += BKK) {
        // load 4 tiles: 128 rows x 8 chunks of 16B each = 1024 chunks/tile
#pragma unroll
        for (int t = 0; t < 4; t++) {
            const __nv_bfloat16* sp = srcs[t] + k0;
            uint32_t dst = sb + t * 16384;
#pragma unroll
            for (int it = 0; it < 4; it++) {
                int id = it * 256 + tid;            // 0..1023
                int r = id >> 3, ck = id & 7;
                uint4 v = *(const uint4*)(sp + (size_t)r * K + ck * 8);
                uint32_t off = (uint32_t)(r * 128 + ((ck ^ (r & 7)) * 16));
                asm volatile("st.shared.v4.b32 [%0], {%1,%2,%3,%4};"
                    :: "r"(dst + off), "r"(v.x), "r"(v.y), "r"(v.z), "r"(v.w));
            }
        }
        __syncthreads();

#pragma unroll
        for (int ks = 0; ks < 4; ks++) {
            // B fragments for 4 n-tiles, hi & lo
            uint32_t bh[4][2], bl[4][2];
#pragma unroll
            for (int nt = 0; nt < 4; nt++) {
                int r = wn + nt * 8 + b_r;
                int ck = ks * 2 + b_c;
                uint32_t off = (uint32_t)(r * 128 + ((ck ^ (r & 7)) * 16));
                ldmx2(bh[nt], sb + 32768 + off);
                ldmx2(bl[nt], sb + 49152 + off);
            }
#pragma unroll
            for (int mt = 0; mt < 4; mt++) {
                int r = wm + mt * 16 + a_r;
                int ck = ks * 2 + a_c;
                uint32_t off = (uint32_t)(r * 128 + ((ck ^ (r & 7)) * 16));
                uint32_t ah[4], al[4];
                ldmx4(ah, sb + 0 + off);
                ldmx4(al, sb + 16384 + off);
#pragma unroll
                for (int nt = 0; nt < 4; nt++) {
                    mma16816(acc[mt][nt], ah, bh[nt]);   // hi*hi
                    mma16816(acc[mt][nt], ah, bl[nt]);   // hi*lo
                    mma16816(acc[mt][nt], al, bh[nt]);   // lo*hi
                }
            }
        }
        __syncthreads();
    }

    // epilogue: m16n8 fragment -> thread rows t/4, t/4+8; cols (t%4)*2
    const int er = lane >> 2, ec = (lane & 3) * 2;
#pragma unroll
    for (int mt = 0; mt < 4; mt++) {
#pragma unroll
        for (int nt = 0; nt < 4; nt++) {
            float* base = C + (size_t)(bm + wm + mt * 16 + er) * N + bn + wn + nt * 8 + ec;
            *(float2*)base = make_float2(acc[mt][nt][0], acc[mt][nt][1]);
            *(float2*)(base + (size_t)8 * N) = make_float2(acc[mt][nt][2], acc[mt][nt][3]);
        }
    }
}

// ---------------------------------------------------------------------------
// Flash attention (fp32, causal) — unchanged from the measured baseline.
// ---------------------------------------------------------------------------
__global__ __launch_bounds__(256) void attn_kernel(
    const float* __restrict__ qkv, float* __restrict__ y)
{
    __shared__ float Qs[QT][HD + 4];
    __shared__ float Ks[KT][HD + 4];
    __shared__ float Vs[KT][HD + 4];
    __shared__ float Ss[QT][KT + 4];
    __shared__ float sm_m[QT], sm_l[QT], sm_a[QT];

    const int tid = threadIdx.x;
    const int qt = blockIdx.x;
    const int g  = blockIdx.y;
    const int bh = blockIdx.z;
    const int b = bh >> 4;
    const int h = bh & 15;

    const size_t rs = CQKV;
    const float* qbase = qkv + (size_t)(b * 1024 + qt * QT) * rs + g * 1024 + h * 64;
    const float* kbase = qkv + (size_t)(b * 1024) * rs + 4 * 1024 + h * 64;
    const float* vbase = qkv + (size_t)(b * 1024) * rs + 5 * 1024 + h * 64;

#pragma unroll
    for (int p = 0; p < 4; p++) {
        int idx = (p * 256 + tid) * 4;
        int r = idx >> 6, d = idx & 63;
        *(float4*)&Qs[r][d] = *(const float4*)(qbase + (size_t)r * rs + d);
    }
    if (tid < QT) { sm_m[tid] = -1e30f; sm_l[tid] = 0.f; }

    float o[4][4];
#pragma unroll
    for (int i = 0; i < 4; i++)
#pragma unroll
        for (int j = 0; j < 4; j++) o[i][j] = 0.f;

    const int nkt = 2 * qt + 2;
    const float scale = 0.125f;

    const int sr  = (tid >> 4) * 4;
    const int sc  = tid & 15;
    const int orr = (tid >> 4) * 4;
    const int oc  = (tid & 15) * 4;
    const int smr = tid >> 2;
    const int sml = tid & 3;

    for (int kt = 0; kt < nkt; kt++) {
        __syncthreads();
#pragma unroll
        for (int p = 0; p < 2; p++) {
            int idx = (p * 256 + tid) * 4;
            int c = idx >> 6, d = idx & 63;
            *(float4*)&Ks[c][d] = *(const float4*)(kbase + (size_t)(kt * KT + c) * rs + d);
            *(float4*)&Vs[c][d] = *(const float4*)(vbase + (size_t)(kt * KT + c) * rs + d);
        }
        __syncthreads();

        {
            float s0[4], s1[4];
#pragma unroll
            for (int i = 0; i < 4; i++) { s0[i] = 0.f; s1[i] = 0.f; }
#pragma unroll
            for (int d = 0; d < HD; d += 4) {
                float4 k0 = *(const float4*)&Ks[sc][d];
                float4 k1 = *(const float4*)&Ks[sc + 16][d];
#pragma unroll
                for (int i = 0; i < 4; i++) {
                    float4 q = *(const float4*)&Qs[sr + i][d];
                    s0[i] += q.x * k0.x + q.y * k0.y + q.z * k0.z + q.w * k0.w;
                    s1[i] += q.x * k1.x + q.y * k1.y + q.z * k1.z + q.w * k1.w;
                }
            }
            int qg0 = qt * QT + sr;
            int kg0 = kt * KT + sc;
#pragma unroll
            for (int i = 0; i < 4; i++) {
                int qg = qg0 + i;
                Ss[sr + i][sc]      = (kg0      <= qg) ? s0[i] * scale : -1e30f;
                Ss[sr + i][sc + 16] = (kg0 + 16 <= qg) ? s1[i] * scale : -1e30f;
            }
        }
        __syncthreads();

        {
            float m_old = sm_m[smr];
            float l_old = sm_l[smr];
            float vals[8];
            float vmax = -1e30f;
#pragma unroll
            for (int j = 0; j < 8; j++) {
                vals[j] = Ss[smr][sml * 8 + j];
                vmax = fmaxf(vmax, vals[j]);
            }
            vmax = fmaxf(vmax, __shfl_xor_sync(0xFFFFFFFFu, vmax, 1));
            vmax = fmaxf(vmax, __shfl_xor_sync(0xFFFFFFFFu, vmax, 2));
            float m_new = fmaxf(m_old, vmax);
            float lsum = 0.f;
#pragma unroll
            for (int j = 0; j < 8; j++) {
                float pv = __expf(vals[j] - m_new);
                Ss[smr][sml * 8 + j] = pv;
                lsum += pv;
            }
            lsum += __shfl_xor_sync(0xFFFFFFFFu, lsum, 1);
            lsum += __shfl_xor_sync(0xFFFFFFFFu, lsum, 2);
            if (sml == 0) {
                float alpha = __expf(m_old - m_new);
                sm_m[smr] = m_new;
                sm_l[smr] = l_old * alpha + lsum;
                sm_a[smr] = alpha;
            }
        }
        __syncthreads();

        {
#pragma unroll
            for (int i = 0; i < 4; i++) {
                float a = sm_a[orr + i];
#pragma unroll
                for (int j = 0; j < 4; j++) o[i][j] *= a;
            }
#pragma unroll
            for (int k = 0; k < KT; k += 4) {
                float4 v0 = *(const float4*)&Vs[k + 0][oc];
                float4 v1 = *(const float4*)&Vs[k + 1][oc];
                float4 v2 = *(const float4*)&Vs[k + 2][oc];
                float4 v3 = *(const float4*)&Vs[k + 3][oc];
#pragma unroll
                for (int i = 0; i < 4; i++) {
                    float4 p4 = *(const float4*)&Ss[orr + i][k];
                    o[i][0] += p4.x * v0.x + p4.y * v1.x + p4.z * v2.x + p4.w * v3.x;
                    o[i][1] += p4.x * v0.y + p4.y * v1.y + p4.z * v2.y + p4.w * v3.y;
                    o[i][2] += p4.x * v0.z + p4.y * v1.z + p4.z * v2.z + p4.w * v3.z;
                    o[i][3] += p4.x * v0.w + p4.y * v1.w + p4.z * v2.w + p4.w * v3.w;
                }
            }
        }
    }

    float* ybase = y + (size_t)(b * 1024 + qt * QT) * CY + g * 1024 + h * 64;
#pragma unroll
    for (int i = 0; i < 4; i++) {
        float inv = 1.f / sm_l[orr + i];
        float4 outv = make_float4(o[i][0] * inv, o[i][1] * inv, o[i][2] * inv, o[i][3] * inv);
        *(float4*)(ybase + (size_t)(orr + i) * CY + oc) = outv;
    }
}

// ---------------------------------------------------------------------------

extern "C" void kernel_launch(void* const* d_in, const int* in_sizes, int n_in,
                              void* d_out, int out_size)
{
    const float* x      = (const float*)d_in[0];   // [8,1024,1024]
    const float* W_attn = (const float*)d_in[1];   // [6144,1024]
    const float* W_proj = (const float*)d_in[2];   // [1024,4096]
    float* out = (float*)d_out;                    // [8,1024,1024]

    float *qkv_ptr, *y_ptr;
    __nv_bfloat16 *xhi, *xlo, *wahi, *walo, *yhi, *ylo, *wphi, *wplo;
    cudaGetSymbolAddress((void**)&qkv_ptr, g_qkv);
    cudaGetSymbolAddress((void**)&y_ptr, g_y);
    cudaGetSymbolAddress((void**)&xhi, g_xhi);
    cudaGetSymbolAddress((void**)&xlo, g_xlo);
    cudaGetSymbolAddress((void**)&wahi, g_wahi);
    cudaGetSymbolAddress((void**)&walo, g_walo);
    cudaGetSymbolAddress((void**)&yhi, g_yhi);
    cudaGetSymbolAddress((void**)&ylo, g_ylo);
    cudaGetSymbolAddress((void**)&wphi, g_wphi);
    cudaGetSymbolAddress((void**)&wplo, g_wplo);

    const int SMEM_GEMM = 4 * 16384;   // 64 KB
    cudaFuncSetAttribute(gemm_mma_kernel,
                         cudaFuncAttributeMaxDynamicSharedMemorySize, SMEM_GEMM);

    // splits for GEMM1
    {
        int n = MB * CX;
        split_kernel<<<n / 1024, 256>>>(x, xhi, xlo, n);
        n = CQKV * CX;
        split_kernel<<<n / 1024, 256>>>(W_attn, wahi, walo, n);
    }
    // 1) qkv = x @ W_attn^T
    {
        dim3 grid(CQKV / 128, MB / 128);
        gemm_mma_kernel<<<grid, 256, SMEM_GEMM>>>(xhi, xlo, wahi, walo, qkv_ptr, MB, CQKV, CX);
    }
    // 2) attention -> y
    {
        dim3 grid(1024 / QT, 4, 128);
        attn_kernel<<<grid, 256>>>(qkv_ptr, y_ptr);
    }
    // splits for GEMM2
    {
        int n = MB * CY;
        split_kernel<<<n / 1024, 256>>>(y_ptr, yhi, ylo, n);
        n = CX * CY;
        split_kernel<<<n / 1024, 256>>>(W_proj, wphi, wplo, n);
    }
    // 3) out = y @ W_proj^T
    {
        dim3 grid(CX / 128, MB / 128);
        gemm_mma_kernel<<<grid, 256, SMEM_GEMM>>>(yhi, ylo, wphi, wplo, out, MB, CX, CY);
    }
}